// round 8
// baseline (speedup 1.0000x reference)
#include <cuda_runtime.h>
#include <cstdint>

// ---------------- problem constants ----------------
#define C_CORES 64
#define D_EMB   128
#define CD      (C_CORES * D_EMB)       // 8192 floats = 32 KB per table

// ---------------- phase-1 geometry ----------------
#define TPB     256                     // 8 warps; warps 0-3 are consumers
#define NGRP    2                       // table-pair groups per block
#define NCW     4                       // consumer warps (2 per group)
#define SROWS   8                       // rows per cp.async stage
#define NSTG    6                       // ring depth
#define STG_FL  (SROWS * 64 + 16)       // floats per stage (rows + assign pad)
#define TAB_FL  (NGRP * 2 * CD)         // 4 tables (A/B per group) = 128 KB
#define SMEM_FL (TAB_FL + NCW * NSTG * STG_FL)

// ---------------- global scratch (zero state; kernel self-restores) ------
__device__ unsigned int g_tab[CD];
__device__ unsigned int g_mask32[2];
__device__ int g_a1, g_d1, g_a3, g_d3;

__device__ __forceinline__ unsigned int enc(float f) {
    unsigned int u = __float_as_uint(f);
    return (u & 0x80000000u) ? ~u : (u | 0x80000000u);
}
__device__ __forceinline__ float dec(unsigned int u) {
    u = (u & 0x80000000u) ? (u & 0x7fffffffu) : ~u;
    return __uint_as_float(u);
}
__device__ __forceinline__ float neg_inf() { return __int_as_float(0xff800000); }

__device__ __forceinline__ uint32_t smem_u32(const void* p) {
    uint32_t a;
    asm("{ .reg .u64 t; cvta.to.shared.u64 t, %1; cvt.u32.u64 %0, t; }" : "=r"(a) : "l"(p));
    return a;
}
__device__ __forceinline__ void cpa8(uint32_t dst, const void* src) {
    asm volatile("cp.async.ca.shared.global [%0], [%1], 8;" :: "r"(dst), "l"(src));
}
__device__ __forceinline__ void cpa16(uint32_t dst, const void* src) {
    asm volatile("cp.async.ca.shared.global [%0], [%1], 16;" :: "r"(dst), "l"(src));
}
__device__ __forceinline__ void cpa_commit() {
    asm volatile("cp.async.commit_group;" ::: "memory");
}
__device__ __forceinline__ void cpa_wait() {
    asm volatile("cp.async.wait_group %0;" :: "n"(NSTG - 1) : "memory");
}

__global__ __launch_bounds__(TPB, 1)
void fused_all(const int*   __restrict__ assign,
               const float* __restrict__ emb,
               const float* __restrict__ padding_emb,
               const float* __restrict__ core_con,
               const float* __restrict__ W_self,
               const float* __restrict__ W_msg,
               const float* __restrict__ bvec,
               float*       __restrict__ out,
               int Q, int chunk)
{
    extern __shared__ float sm[];
    __shared__ unsigned char s_seen[C_CORES];

    const int tid  = threadIdx.x;
    const int wid  = tid >> 5;
    const int lane = tid & 31;
    const int grid = gridDim.x;

    // ---- init: tables to -inf, seen flags ----
    {
        float4 ninf4 = make_float4(neg_inf(), neg_inf(), neg_inf(), neg_inf());
        float4* s4 = (float4*)sm;
        for (int i = tid; i < TAB_FL / 4; i += TPB) s4[i] = ninf4;
        if (tid < C_CORES) s_seen[tid] = 0;
    }
    __syncthreads();

    // ================= phase 1: cp.async-pipelined segment max ============
    if (wid < NCW) {
        const int g    = wid >> 1;           // group 0/1
        const int half = wid & 1;            // column half
        float* tabA = sm + g * (2 * CD);     // even rows
        float* tabB = tabA + CD;             // odd rows
        float* stg  = sm + TAB_FL + wid * (NSTG * STG_FL);
        const uint32_t stg_a = smem_u32(stg);

        // chunk is a multiple of SROWS -> q0 multiple of 8 -> all cp.async
        // gmem sources stay 16B/8B aligned.
        const int q0 = (blockIdx.x * NGRP + g) * chunk;
        const int q1 = (q0 + chunk < Q) ? (q0 + chunk) : Q;
        const int colf = half * 64 + lane * 2;          // owned float col base

        if (q0 < Q) {
            const int nrows = q1 - q0;
            const int nst   = nrows / SROWS;            // full stages

            // prologue: always commit NSTG groups (empty if no data)
#pragma unroll
            for (int s = 0; s < NSTG; s++) {
                if (s < nst) {
                    const int qs = q0 + s * SROWS;
                    const uint32_t sb = stg_a + s * STG_FL * 4;
#pragma unroll
                    for (int r = 0; r < SROWS; r++)
                        cpa8(sb + r * 256 + lane * 8,
                             emb + (size_t)(qs + r) * D_EMB + colf);
                    if (lane < 2)
                        cpa16(sb + SROWS * 256 + lane * 16, assign + qs + lane * 4);
                }
                cpa_commit();
            }

            const bool flag = (lane == 0 && half == 0);

            for (int b = 0; b < nst; b++) {
                cpa_wait();                              // stage b complete
                __syncwarp();

                const int slot = b % NSTG;
                float* stage = stg + slot * STG_FL;
                const int* sa = (const int*)(stage + SROWS * 64);

                int    c[SROWS];
                float2 v[SROWS];
#pragma unroll
                for (int r = 0; r < SROWS; r++) {
                    c[r] = sa[r];
                    v[r] = ((const float2*)(stage + r * 64))[lane];
                }
#pragma unroll
                for (int r = 0; r < SROWS; r++) {
                    // A/B alternation + masked index => provably disjoint chains
                    const int idx = (((c[r] & 63) * D_EMB) + colf) & (CD - 1);
                    float* p = ((r & 1) ? tabB : tabA) + idx;
                    float2 o = *(float2*)p;
                    o.x = fmaxf(o.x, v[r].x);
                    o.y = fmaxf(o.y, v[r].y);
                    *(float2*)p = o;
                    if (flag) s_seen[c[r] & 63] = 1;
                }
                __syncwarp();

                // refill the slot just freed
                const int nb = b + NSTG;
                if (nb < nst) {
                    const int qs = q0 + nb * SROWS;
                    const uint32_t sb = stg_a + slot * STG_FL * 4;
#pragma unroll
                    for (int r = 0; r < SROWS; r++)
                        cpa8(sb + r * 256 + lane * 8,
                             emb + (size_t)(qs + r) * D_EMB + colf);
                    if (lane < 2)
                        cpa16(sb + SROWS * 256 + lane * 16, assign + qs + lane * 4);
                }
                cpa_commit();
            }
            asm volatile("cp.async.wait_group 0;" ::: "memory");

            // guarded tail (< SROWS rows), direct loads
            for (int q = q0 + nst * SROWS; q < q1; q++) {
                int cc = __ldg(assign + q);
                float2 vv = __ldg((const float2*)(emb + (size_t)q * D_EMB + colf));
                const int idx = (((cc & 63) * D_EMB) + colf) & (CD - 1);
                float* p = ((q & 1) ? tabB : tabA) + idx;
                float2 o = *(float2*)p;
                o.x = fmaxf(o.x, vv.x);
                o.y = fmaxf(o.y, vv.y);
                *(float2*)p = o;
                if (flag) s_seen[cc & 63] = 1;
            }
        }
    }
    __syncthreads();

    // ---- merge the 4 tables, fold into global encoded table --------------
    {
        const float4* s4 = (const float4*)sm;
        for (int i = tid; i < CD / 4; i += TPB) {
            float4 m = s4[i];
#pragma unroll
            for (int r = 1; r < 4; r++) {
                float4 o = s4[r * (CD / 4) + i];
                m.x = fmaxf(m.x, o.x); m.y = fmaxf(m.y, o.y);
                m.z = fmaxf(m.z, o.z); m.w = fmaxf(m.w, o.w);
            }
            unsigned int* gp = g_tab + i * 4;
            atomicMax(gp + 0, enc(m.x));
            atomicMax(gp + 1, enc(m.y));
            atomicMax(gp + 2, enc(m.z));
            atomicMax(gp + 3, enc(m.w));
        }
        if (wid == 0) {
            unsigned b0 = __ballot_sync(0xffffffffu, s_seen[lane]      != 0);
            unsigned b1 = __ballot_sync(0xffffffffu, s_seen[lane + 32] != 0);
            if (lane == 0) {
                if (b0) atomicOr(&g_mask32[0], b0);
                if (b1) atomicOr(&g_mask32[1], b1);
            }
        }
    }

    // ================= grid barrier #1 (self-cleaning) =====================
    __threadfence();
    __syncthreads();
    if (blockIdx.x >= C_CORES) {
        if (tid == 0) atomicAdd(&g_a1, 1);
        return;
    }
    if (tid == 0) {
        atomicAdd(&g_a1, 1);
        while (atomicAdd(&g_a1, 0) < grid) __nanosleep(64);
        if (atomicAdd(&g_d1, 1) == C_CORES - 1) {
            atomicExch(&g_a1, 0);
            atomicExch(&g_d1, 0);
        }
        __threadfence();
    }
    __syncthreads();

    // ================= phase 2: decode E + fused GNN (smem reused) =========
    float (*sE)[D_EMB] = (float(*)[D_EMB])sm;        // 32 KB
    float* sMp = sm + CD;                            // 2 x 128
    float* sM  = sm + CD + 2 * D_EMB;                // 128
    float* sO  = sm + CD + 3 * D_EMB;                // 2 x 128

    const int c = blockIdx.x;
    const int t = tid & 127;
    const int s = tid >> 7;                          // 0/1

    unsigned long long mask =
        ((unsigned long long)g_mask32[1] << 32) | (unsigned long long)g_mask32[0];
    {
        const float pad = __ldg(&padding_emb[t]);
#pragma unroll 8
        for (int j = s * 32; j < s * 32 + 32; j++) {
            unsigned int u = g_tab[j * D_EMB + t];
            sE[j][t] = ((mask >> j) & 1ull) ? dec(u) : pad;
        }
    }
    __syncthreads();

    // ---- barrier #3 among the 64 epilogue blocks (g_tab reads done) -------
    if (tid == 0) {
        atomicAdd(&g_a3, 1);
        while (atomicAdd(&g_a3, 0) < C_CORES) __nanosleep(64);
        if (atomicAdd(&g_d3, 1) == C_CORES - 1) {
            atomicExch(&g_a3, 0);
            atomicExch(&g_d3, 0);
        }
        __threadfence();
    }
    __syncthreads();

    // restore zero state for next graph replay
    if (tid < 32) ((uint4*)g_tab)[c * 32 + tid] = make_uint4(0, 0, 0, 0);
    if (c == 0 && tid == 32) { g_mask32[0] = 0u; g_mask32[1] = 0u; }

    // Msum[t] = sum_j con[c,j] * E[j,t]
    {
        float a = 0.f;
#pragma unroll 8
        for (int j = s * 32; j < s * 32 + 32; j++)
            a = fmaf(__ldg(&core_con[c * C_CORES + j]), sE[j][t], a);
        sMp[s * D_EMB + t] = a;
    }
    __syncthreads();
    if (s == 0) sM[t] = sMp[t] + sMp[D_EMB + t];
    __syncthreads();

    // out = relu(E@W_self + Msum@W_msg + b)
    {
        float a0 = 0.f, a1 = 0.f;
#pragma unroll 8
        for (int k = s * 64; k < s * 64 + 64; k++) {
            a0 = fmaf(sE[c][k], __ldg(&W_self[k * D_EMB + t]), a0);
            a1 = fmaf(sM[k],    __ldg(&W_msg [k * D_EMB + t]), a1);
        }
        sO[s * D_EMB + t] = a0 + a1;
    }
    __syncthreads();
    if (s == 0) {
        float r = sO[t] + sO[D_EMB + t] + __ldg(&bvec[t]);
        out[c * D_EMB + t] = fmaxf(r, 0.f);
    }
}

// ---------------- launch ----------------
extern "C" void kernel_launch(void* const* d_in, const int* in_sizes, int n_in,
                              void* d_out, int out_size)
{
    const int*   assign      = (const int*)  d_in[0];
    const float* emb         = (const float*)d_in[1];
    const float* padding_emb = (const float*)d_in[2];
    const float* core_con    = (const float*)d_in[3];
    const float* W_self      = (const float*)d_in[4];
    const float* W_msg       = (const float*)d_in[5];
    const float* bvec        = (const float*)d_in[6];
    float* out = (float*)d_out;

    const int Q = in_sizes[0];

    int nsm = 148;
    cudaDeviceGetAttribute(&nsm, cudaDevAttrMultiProcessorCount, 0);
    if (nsm < C_CORES) nsm = C_CORES;

    const int ngroups = nsm * NGRP;
    int chunk = (Q + ngroups - 1) / ngroups;
    chunk = (chunk + SROWS - 1) & ~(SROWS - 1);   // multiple of 8 -> aligned stages

    const int smem = SMEM_FL * (int)sizeof(float);   // ~178 KB
    cudaFuncSetAttribute(fused_all, cudaFuncAttributeMaxDynamicSharedMemorySize, smem);

    fused_all<<<nsm, TPB, smem>>>(assign, emb, padding_emb, core_con,
                                  W_self, W_msg, bvec, out, Q, chunk);
}

// round 10
// speedup vs baseline: 1.7745x; 1.7745x over previous
#include <cuda_runtime.h>
#include <cstdint>

// ---------------- problem constants ----------------
#define C_CORES 64
#define D_EMB   128
#define CD      (C_CORES * D_EMB)      // 8192
#define TPB     1024
#define NW      (TPB / 32)             // 32 warps per block
#define QCAP    200704                 // per-core bin capacity (>= Q)
#define ATILE   2048                   // pass-A tile (fits smem)

// ---------------- global scratch (zero state; kernel self-restores) ------
__device__ int          g_qids[(size_t)C_CORES * QCAP];   // ~51 MB bins
__device__ int          g_cnt[C_CORES];                   // per-core counts
__device__ unsigned int g_tab[CD];                        // encoded segmax
__device__ int gb1a, gb1d, gb2a, gb2d, gb3a, gb3d;        // barrier counters

__device__ __forceinline__ unsigned int enc(float f) {
    unsigned int u = __float_as_uint(f);
    return (u & 0x80000000u) ? ~u : (u | 0x80000000u);
}
__device__ __forceinline__ float dec(unsigned int u) {
    u = (u & 0x80000000u) ? (u & 0x7fffffffu) : ~u;
    return __uint_as_float(u);
}
__device__ __forceinline__ float neg_inf() { return __int_as_float(0xff800000); }

#define FMAX4(d, v) { d.x = fmaxf(d.x, (v).x); d.y = fmaxf(d.y, (v).y); \
                      d.z = fmaxf(d.z, (v).z); d.w = fmaxf(d.w, (v).w); }

__global__ __launch_bounds__(TPB, 1)
void fused(const int*   __restrict__ assign,
           const float* __restrict__ emb,
           const float* __restrict__ padding_emb,
           const float* __restrict__ core_con,
           const float* __restrict__ W_self,
           const float* __restrict__ W_msg,
           const float* __restrict__ bvec,
           float*       __restrict__ out,
           int Q)
{
    extern __shared__ char smraw[];
    const int tid  = threadIdx.x;
    const int wid  = tid >> 5;
    const int lane = tid & 31;
    const int grid = gridDim.x;

    // ================= pass A: bin qubit ids by core ======================
    {
        int* s_hist = (int*)smraw;             // 64
        int* s_cur  = s_hist + C_CORES;        // 64
        int* s_asn  = s_cur  + C_CORES;        // ATILE

        const int Achunk = (Q + grid - 1) / grid;
        const int qa0 = blockIdx.x * Achunk;
        const int qa1 = min(qa0 + Achunk, Q);

        for (int t0 = qa0; t0 < qa1; t0 += ATILE) {
            const int t1 = min(t0 + ATILE, qa1);
            if (tid < C_CORES) s_hist[tid] = 0;
            __syncthreads();
            for (int i = t0 + tid; i < t1; i += TPB) {
                int c = __ldg(assign + i);
                s_asn[i - t0] = c;
                atomicAdd(&s_hist[c], 1);
            }
            __syncthreads();
            if (tid < C_CORES)
                s_cur[tid] = atomicAdd(&g_cnt[tid], s_hist[tid]);
            __syncthreads();
            for (int i = t0 + tid; i < t1; i += TPB) {
                int c = s_asn[i - t0];
                int idx = atomicAdd(&s_cur[c], 1);
                g_qids[(size_t)c * QCAP + idx] = i;
            }
            __syncthreads();
        }
    }

    // ================= grid barrier 1 (all blocks continue) ===============
    __threadfence();
    __syncthreads();
    if (tid == 0) {
        atomicAdd(&gb1a, 1);
        while (atomicAdd(&gb1a, 0) < grid) __nanosleep(32);
        if (atomicAdd(&gb1d, 1) == grid - 1) {
            atomicExch(&gb1a, 0);
            atomicExch(&gb1d, 0);
        }
        __threadfence();
    }
    __syncthreads();

    // ================= pass B: independent gather-max =====================
    {
        const int gw  = blockIdx.x * NW + wid;
        const int c   = gw & 63;
        const int k   = gw >> 6;
        const int nch = (grid * NW) >> 6;       // chunks per core

        if (k < nch) {
            const int n  = __ldcg(&g_cnt[c]);
            int s0 = (int)(((long long)n * k)       / nch);
            int s1 = (int)(((long long)n * (k + 1)) / nch);
            const int*    list = g_qids + (size_t)c * QCAP;
            const float4* e4   = (const float4*)emb;

            float4 acc = make_float4(neg_inf(), neg_inf(), neg_inf(), neg_inf());

            int i = s0;
            for (; i + 32 <= s1; i += 32) {
                int q32 = __ldg(list + i + lane);
#pragma unroll
                for (int r0 = 0; r0 < 32; r0 += 8) {
                    float4 v[8];
#pragma unroll
                    for (int u = 0; u < 8; u++) {
                        int q = __shfl_sync(0xffffffffu, q32, r0 + u);
                        v[u] = __ldg(e4 + (size_t)q * 32 + lane);   // LDG.128
                    }
#pragma unroll
                    for (int u = 0; u < 8; u++) FMAX4(acc, v[u]);
                }
            }
            const int rem = s1 - i;
            if (rem > 0) {
                int q32 = (lane < rem) ? __ldg(list + i + lane) : 0;
                for (int r = 0; r < rem; r++) {
                    int q = __shfl_sync(0xffffffffu, q32, r);
                    float4 v = __ldg(e4 + (size_t)q * 32 + lane);
                    FMAX4(acc, v);
                }
            }
            if (s1 > s0) {   // fold into encoded global table (no-return REDG)
                unsigned int* gp = g_tab + c * D_EMB + lane * 4;
                atomicMax(gp + 0, enc(acc.x));
                atomicMax(gp + 1, enc(acc.y));
                atomicMax(gp + 2, enc(acc.z));
                atomicMax(gp + 3, enc(acc.w));
            }
        }
    }

    // ================= grid barrier 2 (blocks >= 64 exit) =================
    __threadfence();
    __syncthreads();
    if (blockIdx.x >= C_CORES) {
        if (tid == 0) atomicAdd(&gb2a, 1);
        return;
    }
    if (tid == 0) {
        atomicAdd(&gb2a, 1);
        while (atomicAdd(&gb2a, 0) < grid) __nanosleep(32);
        if (atomicAdd(&gb2d, 1) == C_CORES - 1) {
            atomicExch(&gb2a, 0);
            atomicExch(&gb2d, 0);
        }
        __threadfence();
    }
    __syncthreads();

    // ================= epilogue: decode E + fused GNN =====================
    float (*sE)[D_EMB] = (float(*)[D_EMB])smraw;          // 32 KB
    float* sMp = (float*)smraw + CD;                      // 8 x 128
    float* sM  = sMp + 8 * D_EMB;                         // 128
    float* sO  = sM + D_EMB;                              // 8 x 128

    const int c = blockIdx.x;
    const int t = tid & 127;
    const int s = tid >> 7;                               // 0..7

    {
        const float pad = __ldg(&padding_emb[t]);
#pragma unroll
        for (int j = s * 8; j < s * 8 + 8; j++) {
            int cnt = __ldcg(&g_cnt[j]);
            unsigned int u = __ldcg(&g_tab[j * D_EMB + t]);
            sE[j][t] = (cnt > 0) ? dec(u) : pad;
        }
    }
    __syncthreads();

    // ---- barrier 3 among the 64 epilogue blocks (all reads done) ---------
    if (tid == 0) {
        atomicAdd(&gb3a, 1);
        while (atomicAdd(&gb3a, 0) < C_CORES) __nanosleep(32);
        if (atomicAdd(&gb3d, 1) == C_CORES - 1) {
            atomicExch(&gb3a, 0);
            atomicExch(&gb3d, 0);
        }
        __threadfence();
    }
    __syncthreads();

    // restore zero state for next graph replay
    if (tid < 32) ((uint4*)g_tab)[c * 32 + tid] = make_uint4(0, 0, 0, 0);
    if (c == 0 && tid >= 32 && tid < 32 + C_CORES) g_cnt[tid - 32] = 0;

    // Msum[t] = sum_j con[c,j] * E[j,t]   (8-way split)
    {
        float a = 0.f;
#pragma unroll
        for (int j = s * 8; j < s * 8 + 8; j++)
            a = fmaf(__ldg(&core_con[c * C_CORES + j]), sE[j][t], a);
        sMp[s * D_EMB + t] = a;
    }
    __syncthreads();
    if (s == 0) {
        float m = 0.f;
#pragma unroll
        for (int r = 0; r < 8; r++) m += sMp[r * D_EMB + t];
        sM[t] = m;
    }
    __syncthreads();

    // out = relu(E@W_self + Msum@W_msg + b)   (8-way K split)
    {
        float a0 = 0.f, a1 = 0.f;
#pragma unroll
        for (int kk = s * 16; kk < s * 16 + 16; kk++) {
            a0 = fmaf(sE[c][kk], __ldg(&W_self[kk * D_EMB + t]), a0);
            a1 = fmaf(sM[kk],    __ldg(&W_msg [kk * D_EMB + t]), a1);
        }
        sO[s * D_EMB + t] = a0 + a1;
    }
    __syncthreads();
    if (s == 0) {
        float r = __ldg(&bvec[t]);
#pragma unroll
        for (int q = 0; q < 8; q++) r += sO[q * D_EMB + t];
        out[c * D_EMB + t] = fmaxf(r, 0.f);
    }
}

// ---------------- launch ----------------
extern "C" void kernel_launch(void* const* d_in, const int* in_sizes, int n_in,
                              void* d_out, int out_size)
{
    const int*   assign      = (const int*)  d_in[0];
    const float* emb         = (const float*)d_in[1];
    const float* padding_emb = (const float*)d_in[2];
    const float* core_con    = (const float*)d_in[3];
    const float* W_self      = (const float*)d_in[4];
    const float* W_msg       = (const float*)d_in[5];
    const float* bvec        = (const float*)d_in[6];
    float* out = (float*)d_out;

    const int Q = in_sizes[0];

    int nsm = 148;
    cudaDeviceGetAttribute(&nsm, cudaDevAttrMultiProcessorCount, 0);
    if (nsm < C_CORES) nsm = C_CORES;

    // smem: max(pass A: (64+64+ATILE)*4, epilogue: sE + sMp + sM + sO)
    int smemA = (C_CORES * 2 + ATILE) * (int)sizeof(int);                 // 8704
    int smemE = (CD + 8 * D_EMB + D_EMB + 8 * D_EMB) * (int)sizeof(float); // 41472
    int smem  = (smemA > smemE ? smemA : smemE);

    cudaFuncSetAttribute(fused, cudaFuncAttributeMaxDynamicSharedMemorySize, smem);
    fused<<<nsm, TPB, smem>>>(assign, emb, padding_emb, core_con,
                              W_self, W_msg, bvec, out, Q);
}